// round 7
// baseline (speedup 1.0000x reference)
#include <cuda_runtime.h>
#include <cstdint>

#define Bd 256
#define Sd 512
#define Cd 64
#define Hd 128
#define Gd 512
#define REC_THREADS 256
// plain rec (layer 1)
#define KR 80
#define QR 20
#define QS 12
// fused rec (layer 0 + G1 mma)
#define KR2 56
#define QR2 14
#define QS2 18
#define CH 8            // steps per mma chunk
#define NCH (Sd / CH)   // 64 chunks

typedef unsigned long long u64;
typedef unsigned int u32;

__device__ float g_xg[(size_t)Sd * Bd * Gd];  // xg0 then (in-place) xg1
__device__ u32   g_w1t[(size_t)Gd * Hd];      // Wih1 as tf32
__device__ float g_bs1[Gd];                   // bih1 + bhh1

__device__ __forceinline__ u64 pack2(float x, float y) {
    u64 r; asm("mov.b64 %0, {%1,%2};" : "=l"(r) : "f"(x), "f"(y)); return r;
}
__device__ __forceinline__ void unpack2(u64 v, float& x, float& y) {
    asm("mov.b64 {%0,%1}, %2;" : "=f"(x), "=f"(y) : "l"(v));
}
__device__ __forceinline__ u64 fma2(u64 a, u64 b, u64 c) {
    u64 d; asm("fma.rn.f32x2 %0, %1, %2, %3;" : "=l"(d) : "l"(a), "l"(b), "l"(c)); return d;
}
__device__ __forceinline__ float tanh_fast(float x) {
    float y; asm("tanh.approx.f32 %0, %1;" : "=f"(y) : "f"(x)); return y;
}
__device__ __forceinline__ float hsum2(u64 v) {
    float a, b; unpack2(v, a, b); return a + b;
}
__device__ __forceinline__ u32 to_tf32(float x) {
    u32 r; asm("cvt.rna.tf32.f32 %0, %1;" : "=r"(r) : "f"(x)); return r;
}
__device__ __forceinline__ void mma_tf32(
    float& c0, float& c1, float& c2, float& c3,
    u32 a0, u32 a1, u32 a2, u32 a3, u32 b0, u32 b1)
{
    asm("mma.sync.aligned.m16n8k8.row.col.f32.tf32.tf32.f32 "
        "{%0,%1,%2,%3}, {%4,%5,%6,%7}, {%8,%9}, {%0,%1,%2,%3};"
        : "+f"(c0), "+f"(c1), "+f"(c2), "+f"(c3)
        : "r"(a0), "r"(a1), "r"(a2), "r"(a3), "r"(b0), "r"(b1));
}

// ---------------------------------------------------------------------------
// prep: Wih1 -> tf32, bias sums
// ---------------------------------------------------------------------------
__global__ void prep_kernel(const float* __restrict__ W1,
                            const float* __restrict__ bi,
                            const float* __restrict__ bh)
{
    int i = blockIdx.x * 256 + threadIdx.x;
    if (i < Gd * Hd) g_w1t[i] = to_tf32(W1[i]);
    if (i < Gd) g_bs1[i] = bi[i] + bh[i];
}

// ---------------------------------------------------------------------------
// TF32 input GEMM (layer 0 only now). Same as round 6.
// ---------------------------------------------------------------------------
template <int K, bool X_LAYOUT>
__global__ __launch_bounds__(256) void gemm_tf32_kernel(
    const float* __restrict__ A, const float* __restrict__ W,
    const float* __restrict__ b1, const float* __restrict__ b2,
    float* __restrict__ out)
{
    constexpr int SK = K + 4;
    extern __shared__ u32 sm32[];
    u32* As = sm32;
    u32* Bs = sm32 + 128 * SK;

    const int tid = threadIdx.x;
    const int mt  = blockIdx.x;
    const int nt  = blockIdx.y;

    for (int i = tid; i < 128 * (K / 4); i += 256) {
        int row = i / (K / 4);
        int q   = i % (K / 4);
        int m   = mt * 128 + row;
        const float4* src;
        if (X_LAYOUT) {
            int s = m >> 8, b = m & 255;
            src = (const float4*)(A + ((size_t)b * Sd + s) * K);
        } else {
            src = (const float4*)(A + (size_t)m * K);
        }
        float4 v = src[q];
        u32* dst = &As[row * SK + 4 * q];
        dst[0] = to_tf32(v.x); dst[1] = to_tf32(v.y);
        dst[2] = to_tf32(v.z); dst[3] = to_tf32(v.w);
    }
    for (int i = tid; i < 64 * (K / 4); i += 256) {
        int row = i / (K / 4);
        int q   = i % (K / 4);
        const float4* src = (const float4*)(W + (size_t)(nt * 64 + row) * K);
        float4 v = src[q];
        u32* dst = &Bs[row * SK + 4 * q];
        dst[0] = to_tf32(v.x); dst[1] = to_tf32(v.y);
        dst[2] = to_tf32(v.z); dst[3] = to_tf32(v.w);
    }
    __syncthreads();

    const int wid  = tid >> 5;
    const int lane = tid & 31;
    const int gID  = lane >> 2;
    const int tig  = lane & 3;
    const int wm   = (wid >> 1) * 32;
    const int wn   = (wid & 1) * 32;

    float c[2][4][4];
#pragma unroll
    for (int i = 0; i < 2; i++)
#pragma unroll
        for (int j = 0; j < 4; j++)
#pragma unroll
            for (int q = 0; q < 4; q++) c[i][j][q] = 0.0f;

#pragma unroll
    for (int kb = 0; kb < K / 8; kb++) {
        const int k0 = kb * 8;
        u32 a[2][4];
#pragma unroll
        for (int mi = 0; mi < 2; mi++) {
            int r = wm + mi * 16 + gID;
            a[mi][0] = As[r * SK + k0 + tig];
            a[mi][1] = As[(r + 8) * SK + k0 + tig];
            a[mi][2] = As[r * SK + k0 + tig + 4];
            a[mi][3] = As[(r + 8) * SK + k0 + tig + 4];
        }
        u32 b[4][2];
#pragma unroll
        for (int ni = 0; ni < 4; ni++) {
            int r = wn + ni * 8 + gID;
            b[ni][0] = Bs[r * SK + k0 + tig];
            b[ni][1] = Bs[r * SK + k0 + tig + 4];
        }
#pragma unroll
        for (int mi = 0; mi < 2; mi++)
#pragma unroll
            for (int ni = 0; ni < 4; ni++)
                mma_tf32(c[mi][ni][0], c[mi][ni][1], c[mi][ni][2], c[mi][ni][3],
                         a[mi][0], a[mi][1], a[mi][2], a[mi][3],
                         b[ni][0], b[ni][1]);
    }

#pragma unroll
    for (int ni = 0; ni < 4; ni++) {
        int g = nt * 64 + wn + ni * 8 + 2 * tig;
        float bx = b1[g] + b2[g];
        float by = b1[g + 1] + b2[g + 1];
#pragma unroll
        for (int mi = 0; mi < 2; mi++) {
            size_t m = (size_t)mt * 128 + wm + mi * 16 + gID;
            *(float2*)&out[m * Gd + g]       = make_float2(c[mi][ni][0] + bx, c[mi][ni][1] + by);
            *(float2*)&out[(m + 8) * Gd + g] = make_float2(c[mi][ni][2] + bx, c[mi][ni][3] + by);
        }
    }
}

// ---------------------------------------------------------------------------
// FUSED layer-0 recurrence + layer-1 input GEMM (interleaved tf32 mma).
// 256 threads. Rec identical structure to round-5 but KR2=56 regs of Whh0.
// h chunks (CH=8 steps -> 16 rows) staged tf32 in smem double-buffer;
// each step issues 2 k-slices of the previous chunk's mma against g_w1t.
// xg1 written in-place into xg (rows already consumed by layer-0 rec).
// ---------------------------------------------------------------------------
__global__ __launch_bounds__(REC_THREADS, 1) void fused_rec0_kernel(
    float* __restrict__ xg, const float* __restrict__ Whh)
{
    extern __shared__ char smraw[];
    ulonglong2* Wq = (ulonglong2*)smraw;                       // [QS2*2][256]
    u32*  Ach = (u32*)(smraw + (size_t)QS2 * 2 * 256 * 16);    // [2][16][132]
    float* hb = (float*)((char*)Ach + 2 * 16 * 132 * 4);       // [2][2][132]

    const int t = threadIdx.x;
    const int u = t >> 1;
    const int p = t & 1;
    const int col0 = p * 128 + u;
    const int col1 = 256 + p * 128 + u;
    const int b0 = blockIdx.x * 2;

    const int lane = t & 31;
    const int gID  = lane >> 2;
    const int tig  = lane & 3;
    const int gbase = (t >> 5) * 64;    // warp n-range

    // Whh0 register part
    u64 wA[2 * QR2], wB[2 * QR2];
    {
        const u64* rowA = (const u64*)(Whh + (size_t)col0 * Hd);
        const u64* rowB = (const u64*)(Whh + (size_t)col1 * Hd);
#pragma unroll
        for (int j = 0; j < 2 * QR2; j++) { wA[j] = rowA[j]; wB[j] = rowB[j]; }
    }
#pragma unroll
    for (int j = 0; j < QS2; j++) {
        Wq[(j * 2 + 0) * 256 + t] = *(const ulonglong2*)(Whh + (size_t)col0 * Hd + KR2 + 4 * j);
        Wq[(j * 2 + 1) * 256 + t] = *(const ulonglong2*)(Whh + (size_t)col1 * Hd + KR2 + 4 * j);
    }
    for (int i = t; i < 2 * 2 * 132; i += REC_THREADS) hb[i] = 0.0f;

    float c = 0.0f;
    float acc[8][4];
#pragma unroll
    for (int n = 0; n < 8; n++)
#pragma unroll
        for (int q = 0; q < 4; q++) acc[n][q] = 0.0f;

    __syncthreads();

    float xv00 = xg[(size_t)(b0)*Gd + col0];
    float xv01 = xg[(size_t)(b0 + 1) * Gd + col0];
    float xv10 = xg[(size_t)(b0)*Gd + col1];
    float xv11 = xg[(size_t)(b0 + 1) * Gd + col1];

    // one k8-slice of the pending chunk's mma
    auto mma_slice = [&](int k0, const u32* Ab) {
        u32 a0 = Ab[gID * 132 + 8 * k0 + tig];
        u32 a1 = Ab[(gID + 8) * 132 + 8 * k0 + tig];
        u32 a2 = Ab[gID * 132 + 8 * k0 + tig + 4];
        u32 a3 = Ab[(gID + 8) * 132 + 8 * k0 + tig + 4];
#pragma unroll
        for (int ni = 0; ni < 8; ni++) {
            const u32* wp = g_w1t + (size_t)(gbase + ni * 8 + gID) * Hd + 8 * k0 + tig;
            mma_tf32(acc[ni][0], acc[ni][1], acc[ni][2], acc[ni][3],
                     a0, a1, a2, a3, wp[0], wp[4]);
        }
    };
    // store finished chunk cm's xg1 rows, reset acc
    auto store_acc = [&](int cm) {
        const int s_a = CH * cm + (gID >> 1);
        const int b_a = b0 + (gID & 1);
#pragma unroll
        for (int ni = 0; ni < 8; ni++) {
            int g = gbase + ni * 8 + 2 * tig;
            float2 bv = *(const float2*)&g_bs1[g];
            *(float2*)&xg[((size_t)s_a * Bd + b_a) * Gd + g] =
                make_float2(acc[ni][0] + bv.x, acc[ni][1] + bv.y);
            *(float2*)&xg[((size_t)(s_a + 4) * Bd + b_a) * Gd + g] =
                make_float2(acc[ni][2] + bv.x, acc[ni][3] + bv.y);
#pragma unroll
            for (int q = 0; q < 4; q++) acc[ni][q] = 0.0f;
        }
    };

    for (int ch = 0; ch < NCH; ch++) {
        u32* AbW = Ach + (ch & 1) * 16 * 132;              // write buffer
        const u32* AbR = Ach + ((ch & 1) ^ 1) * 16 * 132;  // read (prev chunk)
#pragma unroll 1
        for (int sl = 0; sl < CH; sl++) {
            const int s = ch * CH + sl;
            float n00 = 0.f, n01 = 0.f, n10 = 0.f, n11 = 0.f;
            if (s + 1 < Sd) {
                size_t base = (size_t)(s + 1) * Bd + b0;
                n00 = xg[base * Gd + col0];
                n01 = xg[(base + 1) * Gd + col0];
                n10 = xg[base * Gd + col1];
                n11 = xg[(base + 1) * Gd + col1];
            }
            const int ph = s & 1;
            const ulonglong2* hq0 = (const ulonglong2*)(hb + (ph * 2 + 0) * 132);
            const ulonglong2* hq1 = (const ulonglong2*)(hb + (ph * 2 + 1) * 132);

            u64 a00e = 0, a00o = 0, a01e = 0, a01o = 0;
            u64 a10e = 0, a10o = 0, a11e = 0, a11o = 0;

#pragma unroll
            for (int j = 0; j < QR2; j++) {
                ulonglong2 hA = hq0[j], hB = hq1[j];
                a00e = fma2(wA[2 * j], hA.x, a00e);
                a00o = fma2(wA[2 * j + 1], hA.y, a00o);
                a01e = fma2(wA[2 * j], hB.x, a01e);
                a01o = fma2(wA[2 * j + 1], hB.y, a01o);
                a10e = fma2(wB[2 * j], hA.x, a10e);
                a10o = fma2(wB[2 * j + 1], hA.y, a10o);
                a11e = fma2(wB[2 * j], hB.x, a11e);
                a11o = fma2(wB[2 * j + 1], hB.y, a11o);
            }
#pragma unroll
            for (int j = 0; j < QS2; j++) {
                ulonglong2 w0 = Wq[(j * 2 + 0) * 256 + t];
                ulonglong2 w1 = Wq[(j * 2 + 1) * 256 + t];
                ulonglong2 hA = hq0[QR2 + j], hB = hq1[QR2 + j];
                a00e = fma2(w0.x, hA.x, a00e);
                a00o = fma2(w0.y, hA.y, a00o);
                a01e = fma2(w0.x, hB.x, a01e);
                a01o = fma2(w0.y, hB.y, a01o);
                a10e = fma2(w1.x, hA.x, a10e);
                a10o = fma2(w1.y, hA.y, a10o);
                a11e = fma2(w1.x, hB.x, a11e);
                a11o = fma2(w1.y, hB.y, a11o);
            }

            float p00 = xv00 + hsum2(a00e) + hsum2(a00o);
            float p01 = xv01 + hsum2(a01e) + hsum2(a01o);
            float p10 = xv10 + hsum2(a10e) + hsum2(a10o);
            float p11 = xv11 + hsum2(a11e) + hsum2(a11o);

            float v00 = fmaf(0.5f, tanh_fast(0.5f * p00), 0.5f);
            float v01 = fmaf(0.5f, tanh_fast(0.5f * p01), 0.5f);
            float a10s = (p == 0) ? p10 : 0.5f * p10;
            float a11s = (p == 0) ? p11 : 0.5f * p11;
            float t10 = tanh_fast(a10s);
            float t11 = tanh_fast(a11s);
            float v10 = (p == 0) ? t10 : fmaf(0.5f, t10, 0.5f);
            float v11 = (p == 0) ? t11 : fmaf(0.5f, t11, 0.5f);

            float send1 = (p == 0) ? v01 : v00;
            float send2 = (p == 0) ? v11 : v10;
            float got1 = __shfl_xor_sync(0xffffffffu, send1, 1);
            float got2 = __shfl_xor_sync(0xffffffffu, send2, 1);

            float iv = (p == 0) ? v00 : got1;
            float fv = (p == 0) ? got1 : v01;
            float gv = (p == 0) ? v10 : got2;
            float ov = (p == 0) ? got2 : v11;

            c = fmaf(fv, c, iv * gv);
            float hn = ov * tanh_fast(c);

            hb[((ph ^ 1) * 2 + p) * 132 + u] = hn;
            AbW[(2 * sl + p) * 132 + u] = to_tf32(hn);   // stage for mma

            // interleaved mma: 2 k-slices of previous chunk
            if (ch > 0) {
                mma_slice(2 * sl, AbR);
                mma_slice(2 * sl + 1, AbR);
            }

            xv00 = n00; xv01 = n01; xv10 = n10; xv11 = n11;
            __syncthreads();
        }
        if (ch > 0) store_acc(ch - 1);
    }
    // drain final chunk
    {
        const u32* AbR = Ach + ((NCH - 1) & 1) * 16 * 132;
#pragma unroll
        for (int k0 = 0; k0 < 16; k0++) mma_slice(k0, AbR);
        store_acc(NCH - 1);
    }
}

// ---------------------------------------------------------------------------
// Plain LSTM recurrence (layer 1) — unchanged KR=80 version.
// ---------------------------------------------------------------------------
__global__ __launch_bounds__(REC_THREADS, 1) void lstm_rec_kernel(
    const float* __restrict__ xg, const float* __restrict__ Whh,
    float* __restrict__ y_last)
{
    extern __shared__ char smraw[];
    ulonglong2* Wq = (ulonglong2*)smraw;
    float* hb = (float*)(smraw + (size_t)QS * 2 * 256 * 16);

    const int t = threadIdx.x;
    const int u = t >> 1;
    const int p = t & 1;
    const int col0 = p * 128 + u;
    const int col1 = 256 + p * 128 + u;
    const int b0 = blockIdx.x * 2;

    u64 wA[2 * QR], wB[2 * QR];
    {
        const u64* rowA = (const u64*)(Whh + (size_t)col0 * Hd);
        const u64* rowB = (const u64*)(Whh + (size_t)col1 * Hd);
#pragma unroll
        for (int j = 0; j < 2 * QR; j++) { wA[j] = rowA[j]; wB[j] = rowB[j]; }
    }
#pragma unroll
    for (int j = 0; j < QS; j++) {
        Wq[(j * 2 + 0) * 256 + t] = *(const ulonglong2*)(Whh + (size_t)col0 * Hd + KR + 4 * j);
        Wq[(j * 2 + 1) * 256 + t] = *(const ulonglong2*)(Whh + (size_t)col1 * Hd + KR + 4 * j);
    }
    for (int i = t; i < 2 * 2 * 132; i += REC_THREADS) hb[i] = 0.0f;

    float c = 0.0f;
    __syncthreads();

    float xv00 = xg[(size_t)(b0)*Gd + col0];
    float xv01 = xg[(size_t)(b0 + 1) * Gd + col0];
    float xv10 = xg[(size_t)(b0)*Gd + col1];
    float xv11 = xg[(size_t)(b0 + 1) * Gd + col1];

    for (int s = 0; s < Sd; s++) {
        float n00 = 0.f, n01 = 0.f, n10 = 0.f, n11 = 0.f;
        if (s + 1 < Sd) {
            size_t base = (size_t)(s + 1) * Bd + b0;
            n00 = xg[base * Gd + col0];
            n01 = xg[(base + 1) * Gd + col0];
            n10 = xg[base * Gd + col1];
            n11 = xg[(base + 1) * Gd + col1];
        }
        const int ph = s & 1;
        const ulonglong2* hq0 = (const ulonglong2*)(hb + (ph * 2 + 0) * 132);
        const ulonglong2* hq1 = (const ulonglong2*)(hb + (ph * 2 + 1) * 132);

        u64 a00e = 0, a00o = 0, a01e = 0, a01o = 0;
        u64 a10e = 0, a10o = 0, a11e = 0, a11o = 0;

#pragma unroll
        for (int j = 0; j < QR; j++) {
            ulonglong2 hA = hq0[j], hB = hq1[j];
            a00e = fma2(wA[2 * j], hA.x, a00e);
            a00o = fma2(wA[2 * j + 1], hA.y, a00o);
            a01e = fma2(wA[2 * j], hB.x, a01e);
            a01o = fma2(wA[2 * j + 1], hB.y, a01o);
            a10e = fma2(wB[2 * j], hA.x, a10e);
            a10o = fma2(wB[2 * j + 1], hA.y, a10o);
            a11e = fma2(wB[2 * j], hB.x, a11e);
            a11o = fma2(wB[2 * j + 1], hB.y, a11o);
        }
#pragma unroll
        for (int j = 0; j < QS; j++) {
            ulonglong2 w0 = Wq[(j * 2 + 0) * 256 + t];
            ulonglong2 w1 = Wq[(j * 2 + 1) * 256 + t];
            ulonglong2 hA = hq0[QR + j], hB = hq1[QR + j];
            a00e = fma2(w0.x, hA.x, a00e);
            a00o = fma2(w0.y, hA.y, a00o);
            a01e = fma2(w0.x, hB.x, a01e);
            a01o = fma2(w0.y, hB.y, a01o);
            a10e = fma2(w1.x, hA.x, a10e);
            a10o = fma2(w1.y, hA.y, a10o);
            a11e = fma2(w1.x, hB.x, a11e);
            a11o = fma2(w1.y, hB.y, a11o);
        }

        float p00 = xv00 + hsum2(a00e) + hsum2(a00o);
        float p01 = xv01 + hsum2(a01e) + hsum2(a01o);
        float p10 = xv10 + hsum2(a10e) + hsum2(a10o);
        float p11 = xv11 + hsum2(a11e) + hsum2(a11o);

        float v00 = fmaf(0.5f, tanh_fast(0.5f * p00), 0.5f);
        float v01 = fmaf(0.5f, tanh_fast(0.5f * p01), 0.5f);
        float a10s = (p == 0) ? p10 : 0.5f * p10;
        float a11s = (p == 0) ? p11 : 0.5f * p11;
        float t10 = tanh_fast(a10s);
        float t11 = tanh_fast(a11s);
        float v10 = (p == 0) ? t10 : fmaf(0.5f, t10, 0.5f);
        float v11 = (p == 0) ? t11 : fmaf(0.5f, t11, 0.5f);

        float send1 = (p == 0) ? v01 : v00;
        float send2 = (p == 0) ? v11 : v10;
        float got1 = __shfl_xor_sync(0xffffffffu, send1, 1);
        float got2 = __shfl_xor_sync(0xffffffffu, send2, 1);

        float iv = (p == 0) ? v00 : got1;
        float fv = (p == 0) ? got1 : v01;
        float gv = (p == 0) ? v10 : got2;
        float ov = (p == 0) ? got2 : v11;

        c = fmaf(fv, c, iv * gv);
        float hn = ov * tanh_fast(c);

        hb[((ph ^ 1) * 2 + p) * 132 + u] = hn;
        if (s == Sd - 1) y_last[(size_t)(b0 + p) * Hd + u] = hn;

        xv00 = n00; xv01 = n01; xv10 = n10; xv11 = n11;
        __syncthreads();
    }
}

// ---------------------------------------------------------------------------
extern "C" void kernel_launch(void* const* d_in, const int* in_sizes, int n_in,
                              void* d_out, int out_size)
{
    const float* x    = (const float*)d_in[0];
    const float* Wih0 = (const float*)d_in[1];
    const float* Whh0 = (const float*)d_in[2];
    const float* bih0 = (const float*)d_in[3];
    const float* bhh0 = (const float*)d_in[4];
    const float* Wih1 = (const float*)d_in[5];
    const float* Whh1 = (const float*)d_in[6];
    const float* bih1 = (const float*)d_in[7];
    const float* bhh1 = (const float*)d_in[8];
    float* out = (float*)d_out;

    float* xg = nullptr;
    cudaGetSymbolAddress((void**)&xg, g_xg);

    const int smem_g0 = (128 * (Cd + 4) + 64 * (Cd + 4)) * 4;
    const int smem_fused = QS2 * 2 * 256 * 16 + 2 * 16 * 132 * 4 + 2 * 2 * 132 * 4; // ~166 KB
    const int smem_rec = QS * 2 * 256 * 16 + 2 * 2 * 132 * (int)sizeof(float);

    cudaFuncSetAttribute((const void*)gemm_tf32_kernel<Cd, true>,
                         cudaFuncAttributeMaxDynamicSharedMemorySize, smem_g0);
    cudaFuncSetAttribute((const void*)fused_rec0_kernel,
                         cudaFuncAttributeMaxDynamicSharedMemorySize, smem_fused);
    cudaFuncSetAttribute((const void*)lstm_rec_kernel,
                         cudaFuncAttributeMaxDynamicSharedMemorySize, smem_rec);

    dim3 ggrid((Sd * Bd) / 128, Gd / 64);

    prep_kernel<<<(Gd * Hd + 255) / 256, 256>>>(Wih1, bih1, bhh1);
    gemm_tf32_kernel<Cd, true><<<ggrid, 256, smem_g0>>>(x, Wih0, bih0, bhh0, xg);
    fused_rec0_kernel<<<Bd / 2, REC_THREADS, smem_fused>>>(xg, Whh0);
    lstm_rec_kernel<<<Bd / 2, REC_THREADS, smem_rec>>>(xg, Whh1, out);
}

// round 10
// speedup vs baseline: 1.5241x; 1.5241x over previous
#include <cuda_runtime.h>
#include <cstdint>

#define Bd 256
#define Sd 512
#define Cd 64
#define Hd 128
#define Gd 512
#define REC_THREADS 256
#define KR 80
#define QR 20
#define QS 12

typedef unsigned long long u64;
typedef unsigned int u32;

__device__ float g_xg[(size_t)Sd * Bd * Gd];
__device__ float g_y1[(size_t)Sd * Bd * Hd];

__device__ __forceinline__ u64 pack2(float x, float y) {
    u64 r; asm("mov.b64 %0, {%1,%2};" : "=l"(r) : "f"(x), "f"(y)); return r;
}
__device__ __forceinline__ void unpack2(u64 v, float& x, float& y) {
    asm("mov.b64 {%0,%1}, %2;" : "=f"(x), "=f"(y) : "l"(v));
}
__device__ __forceinline__ u64 fma2(u64 a, u64 b, u64 c) {
    u64 d; asm("fma.rn.f32x2 %0, %1, %2, %3;" : "=l"(d) : "l"(a), "l"(b), "l"(c)); return d;
}
__device__ __forceinline__ float tanh_fast(float x) {
    float y; asm("tanh.approx.f32 %0, %1;" : "=f"(y) : "f"(x)); return y;
}
__device__ __forceinline__ float hsum2(u64 v) { float a, b; unpack2(v, a, b); return a + b; }
__device__ __forceinline__ void mma_tf32(
    float& c0, float& c1, float& c2, float& c3,
    u32 a0, u32 a1, u32 a2, u32 a3, u32 b0, u32 b1)
{
    asm("mma.sync.aligned.m16n8k8.row.col.f32.tf32.tf32.f32 "
        "{%0,%1,%2,%3}, {%4,%5,%6,%7}, {%8,%9}, {%0,%1,%2,%3};"
        : "+f"(c0), "+f"(c1), "+f"(c2), "+f"(c3)
        : "r"(a0), "r"(a1), "r"(a2), "r"(a3), "r"(b0), "r"(b1));
}
__device__ __forceinline__ void cp16(u32 dst, const void* src) {
    asm volatile("cp.async.cg.shared.global [%0], [%1], 16;" :: "r"(dst), "l"(src));
}
__device__ __forceinline__ u32 smem_u32(const void* p) {
    u32 a; asm("{ .reg .u64 t; cvta.to.shared.u64 t, %1; cvt.u32.u64 %0, t; }" : "=r"(a) : "l"(p));
    return a;
}

// ---------------------------------------------------------------------------
// Pipelined TF32 GEMM: out[m,g] = sum_k A[m,k]*W[g,k] + b1[g] + b2[g]
// CTA tile 128m x 64n, kc=32 double-buffered via cp.async.
// Warps: 4(m) x 2(n); per warp 32m x 32n = 2 x 4 m16n8k8 tiles.
// Smem chunk layout: A [128][36] (fp32 raw bits -> tf32), W [64][36].
// Fragment LDS banks: (4*gID + tig) mod 32 all-distinct -> conflict-free.
// X_LAYOUT=true: A is x (B,S,C), row for m=(s*Bd+b) at (b*Sd+s)*K.
// ---------------------------------------------------------------------------
template <int K, bool X_LAYOUT>
__global__ __launch_bounds__(256) void gemm_tf32_kernel(
    const float* __restrict__ A, const float* __restrict__ W,
    const float* __restrict__ b1, const float* __restrict__ b2,
    float* __restrict__ out)
{
    constexpr int KC = 32;
    constexpr int NC = K / KC;
    constexpr int SK = 36;                 // chunk row stride (floats), 16B aligned
    constexpr int ABUF = 128 * SK;         // floats per A buffer
    constexpr int WBUF = 64 * SK;

    extern __shared__ u32 sm32[];
    const u32 sb = smem_u32(sm32);
    // [A0][A1][W0][W1]
    const u32 sA = sb;
    const u32 sW = sb + 2 * ABUF * 4;

    const int tid = threadIdx.x;
    const int mt  = blockIdx.x;
    const int nt  = blockIdx.y;

    auto fill = [&](int c, int buf) {
        const int k0 = c * KC;
        // A: 128 rows x 8 segs of 16B
#pragma unroll
        for (int r = 0; r < 4; r++) {
            int idx = tid + 256 * r;
            int row = idx >> 3, seg = idx & 7;
            int m = mt * 128 + row;
            const float* arow;
            if (X_LAYOUT) {
                int s = m >> 8, b = m & 255;
                arow = A + ((size_t)b * Sd + s) * K;
            } else {
                arow = A + (size_t)m * K;
            }
            cp16(sA + (buf * ABUF + row * SK + seg * 4) * 4, arow + k0 + seg * 4);
        }
        // W: 64 rows x 8 segs
#pragma unroll
        for (int r = 0; r < 2; r++) {
            int idx = tid + 256 * r;
            int row = idx >> 3, seg = idx & 7;
            const float* wrow = W + (size_t)(nt * 64 + row) * K;
            cp16(sW + (buf * WBUF + row * SK + seg * 4) * 4, wrow + k0 + seg * 4);
        }
        asm volatile("cp.async.commit_group;" ::: "memory");
    };

    const int wid  = tid >> 5;
    const int lane = tid & 31;
    const int gID  = lane >> 2;
    const int tig  = lane & 3;
    const int wm   = (wid >> 1) * 32;
    const int wn   = (wid & 1) * 32;

    float c[2][4][4];
#pragma unroll
    for (int i = 0; i < 2; i++)
#pragma unroll
        for (int j = 0; j < 4; j++)
#pragma unroll
            for (int q = 0; q < 4; q++) c[i][j][q] = 0.0f;

    fill(0, 0);

    for (int ch = 0; ch < NC; ch++) {
        if (ch + 1 < NC) {
            fill(ch + 1, (ch + 1) & 1);
            asm volatile("cp.async.wait_group 1;" ::: "memory");
        } else {
            asm volatile("cp.async.wait_group 0;" ::: "memory");
        }
        __syncthreads();

        const u32* As = sm32 + (ch & 1) * ABUF;
        const u32* Bs = sm32 + 2 * ABUF + (ch & 1) * WBUF;

#pragma unroll
        for (int kb = 0; kb < KC / 8; kb++) {
            const int k0 = kb * 8;
            u32 a[2][4];
#pragma unroll
            for (int mi = 0; mi < 2; mi++) {
                int r = wm + mi * 16 + gID;
                a[mi][0] = As[r * SK + k0 + tig];
                a[mi][1] = As[(r + 8) * SK + k0 + tig];
                a[mi][2] = As[r * SK + k0 + tig + 4];
                a[mi][3] = As[(r + 8) * SK + k0 + tig + 4];
            }
            u32 b[4][2];
#pragma unroll
            for (int ni = 0; ni < 4; ni++) {
                int r = wn + ni * 8 + gID;
                b[ni][0] = Bs[r * SK + k0 + tig];
                b[ni][1] = Bs[r * SK + k0 + tig + 4];
            }
#pragma unroll
            for (int mi = 0; mi < 2; mi++)
#pragma unroll
                for (int ni = 0; ni < 4; ni++)
                    mma_tf32(c[mi][ni][0], c[mi][ni][1], c[mi][ni][2], c[mi][ni][3],
                             a[mi][0], a[mi][1], a[mi][2], a[mi][3],
                             b[ni][0], b[ni][1]);
        }
        __syncthreads();   // protect buffer before it is refilled
    }

    // epilogue: bias + store
#pragma unroll
    for (int ni = 0; ni < 4; ni++) {
        int g = nt * 64 + wn + ni * 8 + 2 * tig;
        float bx = b1[g] + b2[g];
        float by = b1[g + 1] + b2[g + 1];
#pragma unroll
        for (int mi = 0; mi < 2; mi++) {
            size_t m = (size_t)mt * 128 + wm + mi * 16 + gID;
            *(float2*)&out[m * Gd + g]       = make_float2(c[mi][ni][0] + bx, c[mi][ni][1] + by);
            *(float2*)&out[(m + 8) * Gd + g] = make_float2(c[mi][ni][2] + bx, c[mi][ni][3] + by);
        }
    }
}

// ---------------------------------------------------------------------------
// LSTM recurrence (proven round-5/6 core, unchanged).
// ---------------------------------------------------------------------------
__global__ __launch_bounds__(REC_THREADS, 1) void lstm_rec_kernel(
    const float* __restrict__ xg, const float* __restrict__ Whh,
    float* __restrict__ y_all, float* __restrict__ y_last)
{
    extern __shared__ char smraw[];
    ulonglong2* Wq = (ulonglong2*)smraw;
    float* hb = (float*)(smraw + (size_t)QS * 2 * 256 * 16);

    const int t = threadIdx.x;
    const int u = t >> 1;
    const int p = t & 1;
    const int col0 = p * 128 + u;
    const int col1 = 256 + p * 128 + u;
    const int b0 = blockIdx.x * 2;

    u64 wA[2 * QR], wB[2 * QR];
    {
        const u64* rowA = (const u64*)(Whh + (size_t)col0 * Hd);
        const u64* rowB = (const u64*)(Whh + (size_t)col1 * Hd);
#pragma unroll
        for (int j = 0; j < 2 * QR; j++) { wA[j] = rowA[j]; wB[j] = rowB[j]; }
    }
#pragma unroll
    for (int j = 0; j < QS; j++) {
        Wq[(j * 2 + 0) * 256 + t] = *(const ulonglong2*)(Whh + (size_t)col0 * Hd + KR + 4 * j);
        Wq[(j * 2 + 1) * 256 + t] = *(const ulonglong2*)(Whh + (size_t)col1 * Hd + KR + 4 * j);
    }
    for (int i = t; i < 2 * 2 * 132; i += REC_THREADS) hb[i] = 0.0f;

    float c = 0.0f;
    __syncthreads();

    float xv00 = xg[(size_t)(b0)*Gd + col0];
    float xv01 = xg[(size_t)(b0 + 1) * Gd + col0];
    float xv10 = xg[(size_t)(b0)*Gd + col1];
    float xv11 = xg[(size_t)(b0 + 1) * Gd + col1];

    for (int s = 0; s < Sd; s++) {
        float n00 = 0.f, n01 = 0.f, n10 = 0.f, n11 = 0.f;
        if (s + 1 < Sd) {
            size_t base = (size_t)(s + 1) * Bd + b0;
            n00 = xg[base * Gd + col0];
            n01 = xg[(base + 1) * Gd + col0];
            n10 = xg[base * Gd + col1];
            n11 = xg[(base + 1) * Gd + col1];
        }
        const int ph = s & 1;
        const ulonglong2* hq0 = (const ulonglong2*)(hb + (ph * 2 + 0) * 132);
        const ulonglong2* hq1 = (const ulonglong2*)(hb + (ph * 2 + 1) * 132);

        u64 a00e = 0, a00o = 0, a01e = 0, a01o = 0;
        u64 a10e = 0, a10o = 0, a11e = 0, a11o = 0;

#pragma unroll
        for (int j = 0; j < QR; j++) {
            ulonglong2 hA = hq0[j], hB = hq1[j];
            a00e = fma2(wA[2 * j], hA.x, a00e);
            a00o = fma2(wA[2 * j + 1], hA.y, a00o);
            a01e = fma2(wA[2 * j], hB.x, a01e);
            a01o = fma2(wA[2 * j + 1], hB.y, a01o);
            a10e = fma2(wB[2 * j], hA.x, a10e);
            a10o = fma2(wB[2 * j + 1], hA.y, a10o);
            a11e = fma2(wB[2 * j], hB.x, a11e);
            a11o = fma2(wB[2 * j + 1], hB.y, a11o);
        }
#pragma unroll
        for (int j = 0; j < QS; j++) {
            ulonglong2 w0 = Wq[(j * 2 + 0) * 256 + t];
            ulonglong2 w1 = Wq[(j * 2 + 1) * 256 + t];
            ulonglong2 hA = hq0[QR + j], hB = hq1[QR + j];
            a00e = fma2(w0.x, hA.x, a00e);
            a00o = fma2(w0.y, hA.y, a00o);
            a01e = fma2(w0.x, hB.x, a01e);
            a01o = fma2(w0.y, hB.y, a01o);
            a10e = fma2(w1.x, hA.x, a10e);
            a10o = fma2(w1.y, hA.y, a10o);
            a11e = fma2(w1.x, hB.x, a11e);
            a11o = fma2(w1.y, hB.y, a11o);
        }

        float p00 = xv00 + hsum2(a00e) + hsum2(a00o);
        float p01 = xv01 + hsum2(a01e) + hsum2(a01o);
        float p10 = xv10 + hsum2(a10e) + hsum2(a10o);
        float p11 = xv11 + hsum2(a11e) + hsum2(a11o);

        float v00 = fmaf(0.5f, tanh_fast(0.5f * p00), 0.5f);
        float v01 = fmaf(0.5f, tanh_fast(0.5f * p01), 0.5f);
        float a10s = (p == 0) ? p10 : 0.5f * p10;
        float a11s = (p == 0) ? p11 : 0.5f * p11;
        float t10 = tanh_fast(a10s);
        float t11 = tanh_fast(a11s);
        float v10 = (p == 0) ? t10 : fmaf(0.5f, t10, 0.5f);
        float v11 = (p == 0) ? t11 : fmaf(0.5f, t11, 0.5f);

        float send1 = (p == 0) ? v01 : v00;
        float send2 = (p == 0) ? v11 : v10;
        float got1 = __shfl_xor_sync(0xffffffffu, send1, 1);
        float got2 = __shfl_xor_sync(0xffffffffu, send2, 1);

        float iv = (p == 0) ? v00 : got1;
        float fv = (p == 0) ? got1 : v01;
        float gv = (p == 0) ? v10 : got2;
        float ov = (p == 0) ? got2 : v11;

        c = fmaf(fv, c, iv * gv);
        float hn = ov * tanh_fast(c);

        hb[((ph ^ 1) * 2 + p) * 132 + u] = hn;
        if (y_all) {
            y_all[((size_t)s * Bd + b0 + p) * Hd + u] = hn;
        } else if (s == Sd - 1) {
            y_last[(size_t)(b0 + p) * Hd + u] = hn;
        }

        xv00 = n00; xv01 = n01; xv10 = n10; xv11 = n11;
        __syncthreads();
    }
}

// ---------------------------------------------------------------------------
extern "C" void kernel_launch(void* const* d_in, const int* in_sizes, int n_in,
                              void* d_out, int out_size)
{
    const float* x    = (const float*)d_in[0];
    const float* Wih0 = (const float*)d_in[1];
    const float* Whh0 = (const float*)d_in[2];
    const float* bih0 = (const float*)d_in[3];
    const float* bhh0 = (const float*)d_in[4];
    const float* Wih1 = (const float*)d_in[5];
    const float* Whh1 = (const float*)d_in[6];
    const float* bih1 = (const float*)d_in[7];
    const float* bhh1 = (const float*)d_in[8];
    float* out = (float*)d_out;

    float* xg = nullptr;
    float* y1 = nullptr;
    cudaGetSymbolAddress((void**)&xg, g_xg);
    cudaGetSymbolAddress((void**)&y1, g_y1);

    const int smem_gemm = (2 * 128 * 36 + 2 * 64 * 36) * 4;   // 55296 B
    const int smem_rec  = QS * 2 * 256 * 16 + 2 * 2 * 132 * (int)sizeof(float);

    cudaFuncSetAttribute((const void*)gemm_tf32_kernel<Cd, true>,
                         cudaFuncAttributeMaxDynamicSharedMemorySize, smem_gemm);
    cudaFuncSetAttribute((const void*)gemm_tf32_kernel<Hd, false>,
                         cudaFuncAttributeMaxDynamicSharedMemorySize, smem_gemm);
    cudaFuncSetAttribute((const void*)lstm_rec_kernel,
                         cudaFuncAttributeMaxDynamicSharedMemorySize, smem_rec);

    dim3 ggrid((Sd * Bd) / 128, Gd / 64);

    gemm_tf32_kernel<Cd, true><<<ggrid, 256, smem_gemm>>>(x, Wih0, bih0, bhh0, xg);
    lstm_rec_kernel<<<Bd / 2, REC_THREADS, smem_rec>>>(xg, Whh0, y1, nullptr);

    gemm_tf32_kernel<Hd, false><<<ggrid, 256, smem_gemm>>>(y1, Wih1, bih1, bhh1, xg);
    lstm_rec_kernel<<<Bd / 2, REC_THREADS, smem_rec>>>(xg, Whh1, nullptr, out);
}